// round 6
// baseline (speedup 1.0000x reference)
#include <cuda_runtime.h>
#include <math.h>

#define BB 32
#define CC 256
#define HH 56
#define WW 56
#define HWSZ (HH * WW)          // 3136
#define NPIX (BB * HWSZ)        // 100352
#define NELEM (BB * CC * HWSZ)  // 25690112

// Scratch (device globals — no allocation allowed anywhere in this file)
__device__ __align__(16) float g_avg[NPIX];
__device__ __align__(16) float g_mx[NPIX];
__device__ __align__(16) float g_att[NPIX];

// ---------------------------------------------------------------------------
// Kernel 1: channel-wise mean + max. One thread per 2 pixels (float2 loads).
// Per warp per channel step: 32 lanes * 8B = 256B = two full 128B lines.
// Channel-unroll 4 -> 8 outstanding float2 loads per thread for MLP.
// ---------------------------------------------------------------------------
__global__ void reduce_kernel(const float* __restrict__ x) {
    int tid = blockIdx.x * blockDim.x + threadIdx.x;   // index over pixel pairs
    if (tid >= NPIX / 2) return;
    int pix = tid * 2;
    int b = pix / HWSZ;
    int hw = pix - b * HWSZ;
    const float2* p = (const float2*)(x + (size_t)b * CC * HWSZ + hw);
    // channel stride in float2 units: HWSZ/2
    const int cs = HWSZ / 2;

    float2 s0 = make_float2(0.f, 0.f), s1 = make_float2(0.f, 0.f);
    float2 s2 = make_float2(0.f, 0.f), s3 = make_float2(0.f, 0.f);
    float2 m0 = make_float2(-INFINITY, -INFINITY), m1 = m0, m2 = m0, m3 = m0;

#pragma unroll 4
    for (int c = 0; c < CC; c += 4) {
        float2 v0 = __ldg(p + (size_t)(c + 0) * cs);
        float2 v1 = __ldg(p + (size_t)(c + 1) * cs);
        float2 v2 = __ldg(p + (size_t)(c + 2) * cs);
        float2 v3 = __ldg(p + (size_t)(c + 3) * cs);
        s0.x += v0.x; s0.y += v0.y;
        s1.x += v1.x; s1.y += v1.y;
        s2.x += v2.x; s2.y += v2.y;
        s3.x += v3.x; s3.y += v3.y;
        m0.x = fmaxf(m0.x, v0.x); m0.y = fmaxf(m0.y, v0.y);
        m1.x = fmaxf(m1.x, v1.x); m1.y = fmaxf(m1.y, v1.y);
        m2.x = fmaxf(m2.x, v2.x); m2.y = fmaxf(m2.y, v2.y);
        m3.x = fmaxf(m3.x, v3.x); m3.y = fmaxf(m3.y, v3.y);
    }
    float2 avg, mx;
    avg.x = (s0.x + s1.x + s2.x + s3.x) * (1.0f / CC);
    avg.y = (s0.y + s1.y + s2.y + s3.y) * (1.0f / CC);
    mx.x = fmaxf(fmaxf(m0.x, m1.x), fmaxf(m2.x, m3.x));
    mx.y = fmaxf(fmaxf(m0.y, m1.y), fmaxf(m2.y, m3.y));
    *(float2*)(g_avg + pix) = avg;
    *(float2*)(g_mx + pix)  = mx;
}

// ---------------------------------------------------------------------------
// Kernel 2: 7x7 conv over the 2-channel (avg, max) map + sigmoid.
// Tiny: 100K threads * 98 FMAs, data is L2-resident (802 KB).
// ---------------------------------------------------------------------------
__global__ void conv_kernel(const float* __restrict__ cw) {
    int tid = blockIdx.x * blockDim.x + threadIdx.x;
    if (tid >= NPIX) return;
    int b = tid / HWSZ;
    int hw = tid - b * HWSZ;
    int h = hw / WW;
    int w = hw - h * WW;

    const float* base_a = g_avg + b * HWSZ;
    const float* base_m = g_mx + b * HWSZ;

    float acc = 0.f;
#pragma unroll
    for (int kh = 0; kh < 7; kh++) {
        int ih = h + kh - 3;
        if (ih < 0 || ih >= HH) continue;
#pragma unroll
        for (int kw = 0; kw < 7; kw++) {
            int iw = w + kw - 3;
            if (iw < 0 || iw >= WW) continue;
            int off = ih * WW + iw;
            float wa = __ldg(cw + kh * 7 + kw);        // avg-channel weight
            float wm = __ldg(cw + 49 + kh * 7 + kw);   // max-channel weight
            acc = fmaf(base_a[off], wa, acc);
            acc = fmaf(base_m[off], wm, acc);
        }
    }
    g_att[tid] = 1.0f / (1.0f + __expf(-acc));
}

// ---------------------------------------------------------------------------
// Kernel 3: out = x * att (broadcast over C). float4, grid-stride over the
// whole tensor with a grid sized to exactly fill the chip.
// HW=3136 divisible by 4 -> each float4 of x aligns with a float4 of att.
// ---------------------------------------------------------------------------
__global__ void apply_kernel(const float* __restrict__ x, float* __restrict__ out) {
    const int n4 = NELEM / 4;  // 6422528
    for (int i = blockIdx.x * blockDim.x + threadIdx.x; i < n4;
         i += gridDim.x * blockDim.x) {
        int e = i * 4;
        int bc = e / HWSZ;
        int hw = e - bc * HWSZ;
        int b = bc / CC;

        float4 xv = __ldg((const float4*)x + i);
        float4 av = *(const float4*)(g_att + b * HWSZ + hw);

        float4 o;
        o.x = xv.x * av.x;
        o.y = xv.y * av.y;
        o.z = xv.z * av.z;
        o.w = xv.w * av.w;
        ((float4*)out)[i] = o;
    }
}

extern "C" void kernel_launch(void* const* d_in, const int* in_sizes, int n_in,
                              void* d_out, int out_size) {
    const float* x  = (const float*)d_in[0];
    const float* cw = (const float*)d_in[1];
    float* out = (float*)d_out;

    {
        int threads = 256;
        int blocks = (NPIX / 2 + threads - 1) / threads;   // 196 blocks
        reduce_kernel<<<blocks, threads>>>(x);
    }
    {
        int threads = 256;
        int blocks = (NPIX + threads - 1) / threads;       // 392 blocks
        conv_kernel<<<blocks, threads>>>(cw);
    }
    {
        int threads = 256;
        int blocks = 148 * 8;                              // fill the chip
        apply_kernel<<<blocks, threads>>>(x, out);
    }
}

// round 10
// speedup vs baseline: 1.1838x; 1.1838x over previous
#include <cuda_runtime.h>
#include <math.h>

#define BB 32
#define CC 256
#define HH 56
#define WW 56
#define HWSZ (HH * WW)          // 3136
#define NPIX (BB * HWSZ)        // 100352
#define NELEM (BB * CC * HWSZ)  // 25690112

// Scratch (device globals — no allocation allowed anywhere in this file)
__device__ __align__(16) float g_avg[NPIX];
__device__ __align__(16) float g_mx[NPIX];
__device__ __align__(16) float g_att[NPIX];

// ---------------------------------------------------------------------------
// Kernel 1: channel-wise mean + max. One thread per 4 pixels (float4 loads),
// 16 channels unrolled per iteration -> 16 independent LDG.128 in flight per
// thread (8 KB/warp) to cover the ~600-cycle DRAM latency.
// Per warp per load: 32 lanes * 16B = 512B = four full 128B lines.
// ---------------------------------------------------------------------------
__global__ void reduce_kernel(const float* __restrict__ x) {
    int tid = blockIdx.x * blockDim.x + threadIdx.x;   // index over pixel quads
    if (tid >= NPIX / 4) return;
    int pix = tid * 4;
    int b = pix / HWSZ;
    int hw = pix - b * HWSZ;
    const float4* p = (const float4*)(x + (size_t)b * CC * HWSZ + hw);
    const int cs = HWSZ / 4;  // channel stride in float4 units (784)

    float4 s0 = make_float4(0.f, 0.f, 0.f, 0.f);
    float4 s1 = s0, s2 = s0, s3 = s0;
    float4 m0 = make_float4(-INFINITY, -INFINITY, -INFINITY, -INFINITY);
    float4 m1 = m0, m2 = m0, m3 = m0;

    for (int c = 0; c < CC; c += 16) {
        float4 v[16];
#pragma unroll
        for (int j = 0; j < 16; j++)
            v[j] = __ldg(p + (size_t)(c + j) * cs);
#pragma unroll
        for (int j = 0; j < 16; j += 4) {
            s0.x += v[j].x;   s0.y += v[j].y;   s0.z += v[j].z;   s0.w += v[j].w;
            s1.x += v[j+1].x; s1.y += v[j+1].y; s1.z += v[j+1].z; s1.w += v[j+1].w;
            s2.x += v[j+2].x; s2.y += v[j+2].y; s2.z += v[j+2].z; s2.w += v[j+2].w;
            s3.x += v[j+3].x; s3.y += v[j+3].y; s3.z += v[j+3].z; s3.w += v[j+3].w;
            m0.x = fmaxf(m0.x, v[j].x);   m0.y = fmaxf(m0.y, v[j].y);
            m0.z = fmaxf(m0.z, v[j].z);   m0.w = fmaxf(m0.w, v[j].w);
            m1.x = fmaxf(m1.x, v[j+1].x); m1.y = fmaxf(m1.y, v[j+1].y);
            m1.z = fmaxf(m1.z, v[j+1].z); m1.w = fmaxf(m1.w, v[j+1].w);
            m2.x = fmaxf(m2.x, v[j+2].x); m2.y = fmaxf(m2.y, v[j+2].y);
            m2.z = fmaxf(m2.z, v[j+2].z); m2.w = fmaxf(m2.w, v[j+2].w);
            m3.x = fmaxf(m3.x, v[j+3].x); m3.y = fmaxf(m3.y, v[j+3].y);
            m3.z = fmaxf(m3.z, v[j+3].z); m3.w = fmaxf(m3.w, v[j+3].w);
        }
    }

    float4 avg, mx;
    avg.x = (s0.x + s1.x + s2.x + s3.x) * (1.0f / CC);
    avg.y = (s0.y + s1.y + s2.y + s3.y) * (1.0f / CC);
    avg.z = (s0.z + s1.z + s2.z + s3.z) * (1.0f / CC);
    avg.w = (s0.w + s1.w + s2.w + s3.w) * (1.0f / CC);
    mx.x = fmaxf(fmaxf(m0.x, m1.x), fmaxf(m2.x, m3.x));
    mx.y = fmaxf(fmaxf(m0.y, m1.y), fmaxf(m2.y, m3.y));
    mx.z = fmaxf(fmaxf(m0.z, m1.z), fmaxf(m2.z, m3.z));
    mx.w = fmaxf(fmaxf(m0.w, m1.w), fmaxf(m2.w, m3.w));
    *(float4*)(g_avg + pix) = avg;
    *(float4*)(g_mx + pix)  = mx;
}

// ---------------------------------------------------------------------------
// Kernel 2: 7x7 conv over the 2-channel (avg, max) map + sigmoid.
// Tiny: 100K threads * 98 FMAs, data is L2-resident (802 KB).
// ---------------------------------------------------------------------------
__global__ void conv_kernel(const float* __restrict__ cw) {
    int tid = blockIdx.x * blockDim.x + threadIdx.x;
    if (tid >= NPIX) return;
    int b = tid / HWSZ;
    int hw = tid - b * HWSZ;
    int h = hw / WW;
    int w = hw - h * WW;

    const float* base_a = g_avg + b * HWSZ;
    const float* base_m = g_mx + b * HWSZ;

    float acc = 0.f;
#pragma unroll
    for (int kh = 0; kh < 7; kh++) {
        int ih = h + kh - 3;
        if (ih < 0 || ih >= HH) continue;
#pragma unroll
        for (int kw = 0; kw < 7; kw++) {
            int iw = w + kw - 3;
            if (iw < 0 || iw >= WW) continue;
            int off = ih * WW + iw;
            float wa = __ldg(cw + kh * 7 + kw);        // avg-channel weight
            float wm = __ldg(cw + 49 + kh * 7 + kw);   // max-channel weight
            acc = fmaf(base_a[off], wa, acc);
            acc = fmaf(base_m[off], wm, acc);
        }
    }
    g_att[tid] = 1.0f / (1.0f + __expf(-acc));
}

// ---------------------------------------------------------------------------
// Kernel 3: out = x * att (broadcast over C). One thread per float4 — no
// grid-stride loop, so memory parallelism comes from full occupancy instead
// of per-thread unrolling (the loop version serialized to MLP~1).
// HW=3136 divisible by 4 -> each float4 of x aligns with a float4 of att.
// ---------------------------------------------------------------------------
__global__ void apply_kernel(const float* __restrict__ x, float* __restrict__ out) {
    int i = blockIdx.x * blockDim.x + threadIdx.x;   // index over float4s
    if (i >= NELEM / 4) return;
    int e = i * 4;
    int bc = e / HWSZ;
    int hw = e - bc * HWSZ;
    int b = bc / CC;

    float4 xv = __ldg((const float4*)x + i);
    float4 av = *(const float4*)(g_att + b * HWSZ + hw);

    float4 o;
    o.x = xv.x * av.x;
    o.y = xv.y * av.y;
    o.z = xv.z * av.z;
    o.w = xv.w * av.w;
    ((float4*)out)[i] = o;
}

extern "C" void kernel_launch(void* const* d_in, const int* in_sizes, int n_in,
                              void* d_out, int out_size) {
    const float* x  = (const float*)d_in[0];
    const float* cw = (const float*)d_in[1];
    float* out = (float*)d_out;

    {
        int threads = 256;
        int blocks = (NPIX / 4 + threads - 1) / threads;   // 98 blocks
        reduce_kernel<<<blocks, threads>>>(x);
    }
    {
        int threads = 256;
        int blocks = (NPIX + threads - 1) / threads;       // 392 blocks
        conv_kernel<<<blocks, threads>>>(cw);
    }
    {
        int threads = 256;
        int blocks = (NELEM / 4 + threads - 1) / threads;  // 25088 blocks
        apply_kernel<<<blocks, threads>>>(x, out);
    }
}

// round 13
// speedup vs baseline: 1.2960x; 1.0947x over previous
#include <cuda_runtime.h>
#include <math.h>

#define BB 32
#define CC 256
#define HH 56
#define WW 56
#define HWSZ (HH * WW)          // 3136
#define NPIX (BB * HWSZ)        // 100352
#define NPIX4 (NPIX / 4)        // 25088
#define NELEM (BB * CC * HWSZ)  // 25690112
#define G 8                     // channel groups
#define CPG (CC / G)            // 32 channels per group

// Scratch (device globals — no allocation allowed anywhere in this file)
__device__ __align__(16) float g_psum[G * NPIX];   // 3.2 MB
__device__ __align__(16) float g_pmax[G * NPIX];   // 3.2 MB
__device__ __align__(16) float g_avg[NPIX];
__device__ __align__(16) float g_mx[NPIX];
__device__ __align__(16) float g_att[NPIX];

// ---------------------------------------------------------------------------
// Kernel 1a: split-K channel reduction. blockIdx.y = channel group (8 groups
// of 32 channels). Grid = 98 x 8 = 784 blocks -> ~5 blocks/SM, ~32 warps/SM
// resident, so DRAM latency is hidden by warp parallelism, not per-thread ILP.
// Each thread: one pixel-quad (float4), 32 channels, 8 loads in flight.
// ---------------------------------------------------------------------------
__global__ void __launch_bounds__(256) reduce_partial_kernel(const float* __restrict__ x) {
    int i = blockIdx.x * blockDim.x + threadIdx.x;   // pixel-quad index
    if (i >= NPIX4) return;
    int g = blockIdx.y;
    int pix = i * 4;
    int b = pix / HWSZ;
    int hw = pix - b * HWSZ;
    const float4* p = (const float4*)(x + (size_t)b * CC * HWSZ
                                        + (size_t)(g * CPG) * HWSZ + hw);
    const int cs = HWSZ / 4;   // channel stride in float4 units (784)

    float4 s0 = make_float4(0.f, 0.f, 0.f, 0.f), s1 = s0;
    float4 m0 = make_float4(-INFINITY, -INFINITY, -INFINITY, -INFINITY), m1 = m0;

#pragma unroll
    for (int c = 0; c < CPG; c += 8) {
        float4 v[8];
#pragma unroll
        for (int j = 0; j < 8; j++)
            v[j] = __ldg(p + (size_t)(c + j) * cs);
#pragma unroll
        for (int j = 0; j < 8; j += 2) {
            s0.x += v[j].x;   s0.y += v[j].y;   s0.z += v[j].z;   s0.w += v[j].w;
            s1.x += v[j+1].x; s1.y += v[j+1].y; s1.z += v[j+1].z; s1.w += v[j+1].w;
            m0.x = fmaxf(m0.x, v[j].x);   m0.y = fmaxf(m0.y, v[j].y);
            m0.z = fmaxf(m0.z, v[j].z);   m0.w = fmaxf(m0.w, v[j].w);
            m1.x = fmaxf(m1.x, v[j+1].x); m1.y = fmaxf(m1.y, v[j+1].y);
            m1.z = fmaxf(m1.z, v[j+1].z); m1.w = fmaxf(m1.w, v[j+1].w);
        }
    }
    float4 s, m;
    s.x = s0.x + s1.x; s.y = s0.y + s1.y; s.z = s0.z + s1.z; s.w = s0.w + s1.w;
    m.x = fmaxf(m0.x, m1.x); m.y = fmaxf(m0.y, m1.y);
    m.z = fmaxf(m0.z, m1.z); m.w = fmaxf(m0.w, m1.w);
    *(float4*)(g_psum + (size_t)g * NPIX + pix) = s;
    *(float4*)(g_pmax + (size_t)g * NPIX + pix) = m;
}

// ---------------------------------------------------------------------------
// Kernel 1b: combine the 8 partials (L2-resident, 6.4 MB) into avg/max planes.
// ---------------------------------------------------------------------------
__global__ void combine_kernel() {
    int i = blockIdx.x * blockDim.x + threadIdx.x;   // pixel-quad index
    if (i >= NPIX4) return;
    int pix = i * 4;

    float4 s = make_float4(0.f, 0.f, 0.f, 0.f);
    float4 m = make_float4(-INFINITY, -INFINITY, -INFINITY, -INFINITY);
#pragma unroll
    for (int g = 0; g < G; g++) {
        float4 ps = *(const float4*)(g_psum + (size_t)g * NPIX + pix);
        float4 pm = *(const float4*)(g_pmax + (size_t)g * NPIX + pix);
        s.x += ps.x; s.y += ps.y; s.z += ps.z; s.w += ps.w;
        m.x = fmaxf(m.x, pm.x); m.y = fmaxf(m.y, pm.y);
        m.z = fmaxf(m.z, pm.z); m.w = fmaxf(m.w, pm.w);
    }
    float4 avg;
    avg.x = s.x * (1.0f / CC); avg.y = s.y * (1.0f / CC);
    avg.z = s.z * (1.0f / CC); avg.w = s.w * (1.0f / CC);
    *(float4*)(g_avg + pix) = avg;
    *(float4*)(g_mx + pix)  = m;
}

// ---------------------------------------------------------------------------
// Kernel 2: 7x7 conv over the 2-channel (avg, max) map + sigmoid.
// Tiny: 100K threads * 98 FMAs, data is L2-resident (802 KB).
// ---------------------------------------------------------------------------
__global__ void conv_kernel(const float* __restrict__ cw) {
    int tid = blockIdx.x * blockDim.x + threadIdx.x;
    if (tid >= NPIX) return;
    int b = tid / HWSZ;
    int hw = tid - b * HWSZ;
    int h = hw / WW;
    int w = hw - h * WW;

    const float* base_a = g_avg + b * HWSZ;
    const float* base_m = g_mx + b * HWSZ;

    float acc = 0.f;
#pragma unroll
    for (int kh = 0; kh < 7; kh++) {
        int ih = h + kh - 3;
        if (ih < 0 || ih >= HH) continue;
#pragma unroll
        for (int kw = 0; kw < 7; kw++) {
            int iw = w + kw - 3;
            if (iw < 0 || iw >= WW) continue;
            int off = ih * WW + iw;
            float wa = __ldg(cw + kh * 7 + kw);        // avg-channel weight
            float wm = __ldg(cw + 49 + kh * 7 + kw);   // max-channel weight
            acc = fmaf(base_a[off], wa, acc);
            acc = fmaf(base_m[off], wm, acc);
        }
    }
    g_att[tid] = 1.0f / (1.0f + __expf(-acc));
}

// ---------------------------------------------------------------------------
// Kernel 3: out = x * att (broadcast over C). One thread per float4; memory
// parallelism from full occupancy (25088 blocks).
// ---------------------------------------------------------------------------
__global__ void apply_kernel(const float* __restrict__ x, float* __restrict__ out) {
    int i = blockIdx.x * blockDim.x + threadIdx.x;   // float4 index
    if (i >= NELEM / 4) return;
    int e = i * 4;
    int bc = e / HWSZ;
    int hw = e - bc * HWSZ;
    int b = bc / CC;

    float4 xv = __ldg((const float4*)x + i);
    float4 av = *(const float4*)(g_att + b * HWSZ + hw);

    float4 o;
    o.x = xv.x * av.x;
    o.y = xv.y * av.y;
    o.z = xv.z * av.z;
    o.w = xv.w * av.w;
    ((float4*)out)[i] = o;
}

extern "C" void kernel_launch(void* const* d_in, const int* in_sizes, int n_in,
                              void* d_out, int out_size) {
    const float* x  = (const float*)d_in[0];
    const float* cw = (const float*)d_in[1];
    float* out = (float*)d_out;

    {
        dim3 grid((NPIX4 + 255) / 256, G);     // 98 x 8 = 784 blocks
        reduce_partial_kernel<<<grid, 256>>>(x);
    }
    {
        combine_kernel<<<(NPIX4 + 255) / 256, 256>>>();
    }
    {
        conv_kernel<<<(NPIX + 255) / 256, 256>>>(cw);
    }
    {
        apply_kernel<<<(NELEM / 4 + 255) / 256, 256>>>(x, out);
    }
}

// round 14
// speedup vs baseline: 1.6058x; 1.2391x over previous
#include <cuda_runtime.h>
#include <math.h>

#define BB 32
#define CC 256
#define HH 56
#define WW 56
#define HWSZ (HH * WW)          // 3136
#define NPIX (BB * HWSZ)        // 100352
#define NPIX4 (NPIX / 4)        // 25088
#define NELEM (BB * CC * HWSZ)  // 25690112
#define G 8                     // channel groups
#define CPG (CC / G)            // 32 channels per group

// Scratch (device globals — no allocation allowed anywhere in this file)
__device__ __align__(16) float g_psum[G * NPIX];   // 3.2 MB
__device__ __align__(16) float g_pmax[G * NPIX];   // 3.2 MB
__device__ __align__(16) float g_avg[NPIX];
__device__ __align__(16) float g_mx[NPIX];
__device__ __align__(16) float g_att[NPIX];

// ---------------------------------------------------------------------------
// Kernel 1a: split-K channel reduction. blockIdx.y = channel group (8 groups
// of 32 channels). 784 blocks -> ~32 warps/SM resident; DRAM latency hidden
// by warp parallelism. x is read with default .ca so it STAYS in L2 for the
// apply kernel (x 102.8 MB + scratch ~8 MB < 126 MB L2). Partial results are
// stored with .cs (evict-first) so they don't displace x.
// ---------------------------------------------------------------------------
__global__ void __launch_bounds__(256) reduce_partial_kernel(const float* __restrict__ x) {
    int i = blockIdx.x * blockDim.x + threadIdx.x;   // pixel-quad index
    if (i >= NPIX4) return;
    int g = blockIdx.y;
    int pix = i * 4;
    int b = pix / HWSZ;
    int hw = pix - b * HWSZ;
    const float4* p = (const float4*)(x + (size_t)b * CC * HWSZ
                                        + (size_t)(g * CPG) * HWSZ + hw);
    const int cs = HWSZ / 4;   // channel stride in float4 units (784)

    float4 s0 = make_float4(0.f, 0.f, 0.f, 0.f), s1 = s0;
    float4 m0 = make_float4(-INFINITY, -INFINITY, -INFINITY, -INFINITY), m1 = m0;

#pragma unroll
    for (int c = 0; c < CPG; c += 8) {
        float4 v[8];
#pragma unroll
        for (int j = 0; j < 8; j++)
            v[j] = __ldg(p + (size_t)(c + j) * cs);
#pragma unroll
        for (int j = 0; j < 8; j += 2) {
            s0.x += v[j].x;   s0.y += v[j].y;   s0.z += v[j].z;   s0.w += v[j].w;
            s1.x += v[j+1].x; s1.y += v[j+1].y; s1.z += v[j+1].z; s1.w += v[j+1].w;
            m0.x = fmaxf(m0.x, v[j].x);   m0.y = fmaxf(m0.y, v[j].y);
            m0.z = fmaxf(m0.z, v[j].z);   m0.w = fmaxf(m0.w, v[j].w);
            m1.x = fmaxf(m1.x, v[j+1].x); m1.y = fmaxf(m1.y, v[j+1].y);
            m1.z = fmaxf(m1.z, v[j+1].z); m1.w = fmaxf(m1.w, v[j+1].w);
        }
    }
    float4 s, m;
    s.x = s0.x + s1.x; s.y = s0.y + s1.y; s.z = s0.z + s1.z; s.w = s0.w + s1.w;
    m.x = fmaxf(m0.x, m1.x); m.y = fmaxf(m0.y, m1.y);
    m.z = fmaxf(m0.z, m1.z); m.w = fmaxf(m0.w, m1.w);
    __stcs((float4*)(g_psum + (size_t)g * NPIX + pix), s);
    __stcs((float4*)(g_pmax + (size_t)g * NPIX + pix), m);
}

// ---------------------------------------------------------------------------
// Kernel 1b: combine the 8 partials into avg/max planes. Partials are read
// with .cs (dead after this) so they release their L2 footprint.
// ---------------------------------------------------------------------------
__global__ void combine_kernel() {
    int i = blockIdx.x * blockDim.x + threadIdx.x;   // pixel-quad index
    if (i >= NPIX4) return;
    int pix = i * 4;

    float4 s = make_float4(0.f, 0.f, 0.f, 0.f);
    float4 m = make_float4(-INFINITY, -INFINITY, -INFINITY, -INFINITY);
#pragma unroll
    for (int g = 0; g < G; g++) {
        float4 ps = __ldcs((const float4*)(g_psum + (size_t)g * NPIX + pix));
        float4 pm = __ldcs((const float4*)(g_pmax + (size_t)g * NPIX + pix));
        s.x += ps.x; s.y += ps.y; s.z += ps.z; s.w += ps.w;
        m.x = fmaxf(m.x, pm.x); m.y = fmaxf(m.y, pm.y);
        m.z = fmaxf(m.z, pm.z); m.w = fmaxf(m.w, pm.w);
    }
    float4 avg;
    avg.x = s.x * (1.0f / CC); avg.y = s.y * (1.0f / CC);
    avg.z = s.z * (1.0f / CC); avg.w = s.w * (1.0f / CC);
    *(float4*)(g_avg + pix) = avg;
    *(float4*)(g_mx + pix)  = m;
}

// ---------------------------------------------------------------------------
// Kernel 2: 7x7 conv over the 2-channel (avg, max) map + sigmoid.
// Tiny: 100K threads * 98 FMAs, data is L2-resident (802 KB).
// ---------------------------------------------------------------------------
__global__ void conv_kernel(const float* __restrict__ cw) {
    int tid = blockIdx.x * blockDim.x + threadIdx.x;
    if (tid >= NPIX) return;
    int b = tid / HWSZ;
    int hw = tid - b * HWSZ;
    int h = hw / WW;
    int w = hw - h * WW;

    const float* base_a = g_avg + b * HWSZ;
    const float* base_m = g_mx + b * HWSZ;

    float acc = 0.f;
#pragma unroll
    for (int kh = 0; kh < 7; kh++) {
        int ih = h + kh - 3;
        if (ih < 0 || ih >= HH) continue;
#pragma unroll
        for (int kw = 0; kw < 7; kw++) {
            int iw = w + kw - 3;
            if (iw < 0 || iw >= WW) continue;
            int off = ih * WW + iw;
            float wa = __ldg(cw + kh * 7 + kw);        // avg-channel weight
            float wm = __ldg(cw + 49 + kh * 7 + kw);   // max-channel weight
            acc = fmaf(base_a[off], wa, acc);
            acc = fmaf(base_m[off], wm, acc);
        }
    }
    g_att[tid] = 1.0f / (1.0f + __expf(-acc));
}

// ---------------------------------------------------------------------------
// Kernel 3: out = x * att (broadcast over C).
//  - Block order REVERSED: the tail of x (most recently streamed through L2
//    by the reduce) is consumed first, maximizing L2 hits under LRU.
//  - x read with .cs (last use), out stored with .cs (never re-read) so the
//    output stream does not evict the still-unread portion of x from L2.
// ---------------------------------------------------------------------------
__global__ void apply_kernel(const float* __restrict__ x, float* __restrict__ out) {
    int blk = gridDim.x - 1 - blockIdx.x;            // reversed traversal
    int i = blk * blockDim.x + threadIdx.x;          // float4 index
    if (i >= NELEM / 4) return;
    int e = i * 4;
    int bc = e / HWSZ;
    int hw = e - bc * HWSZ;
    int b = bc / CC;

    float4 xv = __ldcs((const float4*)x + i);
    float4 av = *(const float4*)(g_att + b * HWSZ + hw);

    float4 o;
    o.x = xv.x * av.x;
    o.y = xv.y * av.y;
    o.z = xv.z * av.z;
    o.w = xv.w * av.w;
    __stcs((float4*)out + i, o);
}

extern "C" void kernel_launch(void* const* d_in, const int* in_sizes, int n_in,
                              void* d_out, int out_size) {
    const float* x  = (const float*)d_in[0];
    const float* cw = (const float*)d_in[1];
    float* out = (float*)d_out;

    {
        dim3 grid((NPIX4 + 255) / 256, G);     // 98 x 8 = 784 blocks
        reduce_partial_kernel<<<grid, 256>>>(x);
    }
    {
        combine_kernel<<<(NPIX4 + 255) / 256, 256>>>();
    }
    {
        conv_kernel<<<(NPIX + 255) / 256, 256>>>(cw);
    }
    {
        apply_kernel<<<(NELEM / 4 + 255) / 256, 256>>>(x, out);
    }
}